// round 5
// baseline (speedup 1.0000x reference)
#include <cuda_runtime.h>
#include <cstdint>

// Problem constants
#define KC 512
#define DC 256
#define BC 32
#define TC 4096

#define BT 128        // t rows per CTA
#define KT 64         // k per smem tile
#define WS_STRIDE 260 // floats per k-row in smem (256 + 4 pad; 260 % 32 == 4 -> conflict-free)

// smem (floats): Zs 256*128=32768, Ws 64*260=16640, wq 512, zq 128
#define SMEM_FLOATS (DC*BT + KT*WS_STRIDE + KC + BT)

__global__ __launch_bounds__(256, 1)
void vq_argmin_kernel(const float* __restrict__ z,
                      const float* __restrict__ w,
                      float* __restrict__ out)
{
    extern __shared__ float smem[];
    float* Zs  = smem;                      // [d][t], stride BT=128 (exact fp32)
    float* Ws  = Zs + DC * BT;              // [k][d], stride 260    (exact fp32)
    float* wq  = Ws + KT * WS_STRIDE;       // ||w_k||^2, [512]
    float* zqs = wq + KC;                   // ||z_t||^2, [128] (XLA-order serial sum)

    const int tid = threadIdx.x;
    const int b   = blockIdx.y;
    const int t0  = blockIdx.x * BT;

    // ---- Stage Z block [256 d][128 t] into smem (coalesced, exact copy) ----
    {
        const float4* zg = (const float4*)(z + (size_t)b * DC * TC + t0);
        #pragma unroll
        for (int i = 0; i < (DC * BT / 4) / 256; ++i) {   // 32 iters
            int f = tid + 256 * i;
            int d = f >> 5;        // f / 32
            int c = f & 31;
            float4 v = zg[(size_t)d * (TC / 4) + c];
            *(float4*)&Zs[d * BT + c * 4] = v;
        }
    }

    // ---- ||w_k||^2 for all 512 k (exact fp32; order-insensitive at 3e-4 scale) ----
    #pragma unroll
    for (int r = 0; r < 2; ++r) {
        int k = tid + 256 * r;
        const float4* wr = (const float4*)(w + (size_t)k * DC);
        float s = 0.f;
        #pragma unroll
        for (int c = 0; c < DC / 4; ++c) {
            float4 v = wr[c];
            s += v.x * v.x + v.y * v.y + v.z * v.z + v.w * v.w;
        }
        wq[k] = s;
    }
    __syncthreads();

    // ---- ||z_t||^2: replicate XLA column-reduce — SERIAL in-order over d,
    //      separate mul/add roundings (no FMA contraction). Critical: this sum
    //      reaches ~256 and its low-order bits decide near-tie argmins. ----
    if (tid < BT) {
        float s = 0.f;
        #pragma unroll 8
        for (int d = 0; d < DC; ++d) {
            float v = Zs[d * BT + tid];          // bank = tid%32, conflict-free
            s = __fadd_rn(s, __fmul_rn(v, v));
        }
        zqs[tid] = s;
    }
    __syncthreads();

    const int tx = tid & 7;   // k lane (0..7)
    const int ty = tid >> 3;  // t group (0..31), each owns 4 t rows

    float zq[4];
    #pragma unroll
    for (int i = 0; i < 4; ++i) zq[i] = zqs[ty * 4 + i];

    float best[4];
    int   bidx[4];
    #pragma unroll
    for (int i = 0; i < 4; ++i) { best[i] = 3.402823466e38f; bidx[i] = 0; }

    for (int kt = 0; kt < KC / KT; ++kt) {
        // ---- Stage W tile [64 k][256 d] (coalesced load, padded store) ----
        {
            const float4* wg = (const float4*)(w + (size_t)(kt * KT) * DC);
            #pragma unroll
            for (int i = 0; i < (KT * DC / 4) / 256; ++i) {   // 16 iters
                int f = tid + 256 * i;
                int k = f >> 6;     // f / 64
                int c = f & 63;
                float4 v = wg[(size_t)k * (DC / 4) + c];
                *(float4*)&Ws[k * WS_STRIDE + c * 4] = v;
            }
        }
        __syncthreads();

        // ---- 128t x 64k x 256d sub-GEMM, per-thread 4t x 8k (exact fp32) ----
        float acc[4][8];
        #pragma unroll
        for (int i = 0; i < 4; ++i)
            #pragma unroll
            for (int j = 0; j < 8; ++j) acc[i][j] = 0.f;

        #pragma unroll 2
        for (int d4 = 0; d4 < DC / 4; ++d4) {
            float4 zv[4];  // zv[dd] = z[t=ty*4..+3] at d = 4*d4+dd
            #pragma unroll
            for (int dd = 0; dd < 4; ++dd)
                zv[dd] = *(const float4*)&Zs[(d4 * 4 + dd) * BT + ty * 4];

            #pragma unroll
            for (int j = 0; j < 8; ++j) {
                // k_local = tx + 8*j : 8-lane stride-260 float4 -> conflict-free
                float4 wv = *(const float4*)&Ws[(tx + 8 * j) * WS_STRIDE + d4 * 4];
                const float* wc = (const float*)&wv;
                #pragma unroll
                for (int dd = 0; dd < 4; ++dd) {
                    const float* zc = (const float*)&zv[dd];
                    #pragma unroll
                    for (int i = 0; i < 4; ++i)
                        acc[i][j] += zc[i] * wc[dd];
                }
            }
        }

        // ---- Epilogue: replicate reference rounding exactly:
        //      dists = fl(fl(z_sq - fl(2*cross)) + w_sq), then running argmin
        //      with first-index tie-break (ascending k, strict <). ----
        #pragma unroll
        for (int j = 0; j < 8; ++j) {
            int k = kt * KT + tx + 8 * j;
            float h = wq[k];
            #pragma unroll
            for (int i = 0; i < 4; ++i) {
                float c2 = __fmul_rn(2.0f, acc[i][j]);   // exact
                float t2 = __fsub_rn(zq[i], c2);         // rounding @ ~256
                float s  = __fadd_rn(t2, h);             // rounding @ ~256
                if (s < best[i]) { best[i] = s; bidx[i] = k; }
            }
        }
        __syncthreads();  // before overwriting Ws
    }

    // ---- Reduce across the 8 k-lanes (width-8 xor shuffle), min + lowest idx ----
    #pragma unroll
    for (int i = 0; i < 4; ++i) {
        #pragma unroll
        for (int off = 4; off > 0; off >>= 1) {
            float ob = __shfl_xor_sync(0xffffffffu, best[i], off, 8);
            int   oi = __shfl_xor_sync(0xffffffffu, bidx[i], off, 8);
            if (ob < best[i] || (ob == best[i] && oi < bidx[i])) {
                best[i] = ob; bidx[i] = oi;
            }
        }
    }

    if (tx == 0) {
        #pragma unroll
        for (int i = 0; i < 4; ++i)
            out[(size_t)b * TC + t0 + ty * 4 + i] = (float)bidx[i];
    }
}

extern "C" void kernel_launch(void* const* d_in, const int* in_sizes, int n_in,
                              void* d_out, int out_size)
{
    // Identify inputs by size: z_e_x has B*D*T = 33,554,432 elems,
    // emb_weight has K*D = 131,072 elems.
    const float* z = (const float*)d_in[0];
    const float* w = (const float*)d_in[1];
    if (n_in >= 2 && in_sizes[0] == KC * DC && in_sizes[1] == BC * DC * TC) {
        z = (const float*)d_in[1];
        w = (const float*)d_in[0];
    }
    float* out = (float*)d_out;               // [B, T], argmin indices as float32

    (void)out_size;

    cudaFuncSetAttribute(vq_argmin_kernel,
                         cudaFuncAttributeMaxDynamicSharedMemorySize,
                         SMEM_FLOATS * sizeof(float));

    dim3 grid(TC / BT, BC);   // (32, 32)
    vq_argmin_kernel<<<grid, 256, SMEM_FLOATS * sizeof(float)>>>(z, w, out);
}

// round 6
// speedup vs baseline: 1.0208x; 1.0208x over previous
#include <cuda_runtime.h>
#include <cstdint>

// Problem constants
#define KC 512
#define DC 256
#define BC 32
#define TC 4096

#define BT 128        // t rows per CTA
#define KT 64         // k per smem tile
#define S  260        // row stride in floats (256 + 4; keeps float4 alignment, spreads banks)

// smem (floats): Zst 128*260=33280, Ws 64*260=16640, wq 512, zqs 128  -> 50560 fl = 202240 B
// Ztmp (32*128=4096 floats) aliases the Ws region during Z staging.
#define SMEM_FLOATS (BT*S + KT*S + KC + BT)

union F4 { float4 v; unsigned long long u[2]; };
union U2 { unsigned long long u; float f[2]; };

// Packed dual-FMA: {a0,a1}*{b0,b1} + {c0,c1} elementwise, fp32 exact (2x scalar FFMA).
__device__ __forceinline__ void ffma2(unsigned long long& acc,
                                      unsigned long long a,
                                      unsigned long long b) {
    asm("fma.rn.f32x2 %0, %1, %2, %0;" : "+l"(acc) : "l"(a), "l"(b));
}

__global__ __launch_bounds__(256, 1)
void vq_argmin_kernel(const float* __restrict__ z,
                      const float* __restrict__ w,
                      float* __restrict__ out)
{
    extern __shared__ float smem[];
    float* Zst = smem;                 // [t][d], stride S (d-contiguous!)
    float* Ws  = Zst + BT * S;         // [k][d], stride S (d-contiguous)
    float* Ztmp = Ws;                  // [32 d][128 t], aliases Ws during Z staging
    float* wq  = Ws + KT * S;          // ||w_k||^2, [512]
    float* zqs = wq + KC;              // ||z_t||^2, [128]

    const int tid = threadIdx.x;
    const int b   = blockIdx.y;
    const int t0  = blockIdx.x * BT;

    // ---- Stage Z transposed: global [d][t] -> Zst[t][d], via 8 chunks of 32 d ----
    {
        const float4* zg4 = (const float4*)(z + (size_t)b * DC * TC + t0);
        const int tloc = tid & 127;
        const int g    = tid >> 7;            // 0..1
        for (int c8 = 0; c8 < 8; ++c8) {
            // coalesced load chunk [32 d][128 t] into Ztmp
            #pragma unroll
            for (int it = 0; it < 4; ++it) {
                int f = tid + 256 * it;       // 0..1023
                int d = f >> 5;               // 0..31
                int c = f & 31;               // float4 col over t
                float4 v = zg4[(size_t)(c8 * 32 + d) * (TC / 4) + c];
                *(float4*)&Ztmp[d * BT + c * 4] = v;
            }
            __syncthreads();
            // transpose chunk into Zst[t][c8*32 ..]
            #pragma unroll
            for (int qq = 0; qq < 4; ++qq) {
                int q = g * 4 + qq;           // 0..7 -> d-quad within chunk
                float4 o;
                o.x = Ztmp[(q * 4 + 0) * BT + tloc];
                o.y = Ztmp[(q * 4 + 1) * BT + tloc];
                o.z = Ztmp[(q * 4 + 2) * BT + tloc];
                o.w = Ztmp[(q * 4 + 3) * BT + tloc];
                *(float4*)&Zst[tloc * S + c8 * 32 + q * 4] = o;
            }
            __syncthreads();
        }
    }

    // ---- ||w_k||^2 for all 512 k (exact fp32) ----
    #pragma unroll
    for (int r = 0; r < 2; ++r) {
        int k = tid + 256 * r;
        const float4* wr = (const float4*)(w + (size_t)k * DC);
        float s = 0.f;
        #pragma unroll
        for (int c = 0; c < DC / 4; ++c) {
            float4 v = wr[c];
            s += v.x * v.x + v.y * v.y + v.z * v.z + v.w * v.w;
        }
        wq[k] = s;
    }
    __syncthreads();

    // ---- ||z_t||^2: SERIAL in-order over d, separate mul/add roundings.
    //      Bit-identical to the validated Round-5 computation. ----
    if (tid < BT) {
        float s = 0.f;
        #pragma unroll 8
        for (int d = 0; d < DC; ++d) {
            float v = Zst[tid * S + d];
            s = __fadd_rn(s, __fmul_rn(v, v));
        }
        zqs[tid] = s;
    }
    __syncthreads();

    const int tx = tid & 7;   // k lane (0..7)
    const int ty = tid >> 3;  // t group (0..31), each owns 4 t rows

    float zq[4];
    #pragma unroll
    for (int i = 0; i < 4; ++i) zq[i] = zqs[ty * 4 + i];

    float best[4];
    int   bidx[4];
    #pragma unroll
    for (int i = 0; i < 4; ++i) { best[i] = 3.402823466e38f; bidx[i] = 0; }

    const float* zrow0 = &Zst[(ty * 4 + 0) * S];
    const float* zrow1 = &Zst[(ty * 4 + 1) * S];
    const float* zrow2 = &Zst[(ty * 4 + 2) * S];
    const float* zrow3 = &Zst[(ty * 4 + 3) * S];

    for (int kt = 0; kt < KC / KT; ++kt) {
        // ---- Stage W tile [64 k][256 d] (coalesced, d-contiguous rows) ----
        {
            const float4* wg = (const float4*)(w + (size_t)(kt * KT) * DC);
            #pragma unroll
            for (int i = 0; i < (KT * DC / 4) / 256; ++i) {   // 16 iters
                int f = tid + 256 * i;
                int k = f >> 6;     // f / 64
                int c = f & 63;
                float4 v = wg[(size_t)k * (DC / 4) + c];
                *(float4*)&Ws[k * S + c * 4] = v;
            }
        }
        __syncthreads();

        // ---- 128t x 64k x 256d sub-GEMM via packed f32x2 over the d dim ----
        unsigned long long acc[4][8];
        #pragma unroll
        for (int i = 0; i < 4; ++i)
            #pragma unroll
            for (int j = 0; j < 8; ++j) acc[i][j] = 0ull;

        #pragma unroll 2
        for (int d4 = 0; d4 < DC / 4; ++d4) {
            F4 zr[4];
            zr[0].v = *(const float4*)&zrow0[d4 * 4];
            zr[1].v = *(const float4*)&zrow1[d4 * 4];
            zr[2].v = *(const float4*)&zrow2[d4 * 4];
            zr[3].v = *(const float4*)&zrow3[d4 * 4];

            #pragma unroll
            for (int j = 0; j < 8; ++j) {
                F4 wr;
                wr.v = *(const float4*)&Ws[(tx + 8 * j) * S + d4 * 4];
                #pragma unroll
                for (int i = 0; i < 4; ++i) {
                    ffma2(acc[i][j], zr[i].u[0], wr.u[0]);
                    ffma2(acc[i][j], zr[i].u[1], wr.u[1]);
                }
            }
        }

        // ---- Epilogue: cross = lo+hi; exact reference rounding sequence;
        //      running argmin with first-index tie-break ----
        #pragma unroll
        for (int j = 0; j < 8; ++j) {
            int k = kt * KT + tx + 8 * j;
            float h = wq[k];
            #pragma unroll
            for (int i = 0; i < 4; ++i) {
                U2 u; u.u = acc[i][j];
                float cross = u.f[0] + u.f[1];
                float c2 = __fmul_rn(2.0f, cross);
                float t2 = __fsub_rn(zq[i], c2);
                float s  = __fadd_rn(t2, h);
                if (s < best[i]) { best[i] = s; bidx[i] = k; }
            }
        }
        __syncthreads();  // before overwriting Ws
    }

    // ---- Reduce across the 8 k-lanes (width-8 xor shuffle), min + lowest idx ----
    #pragma unroll
    for (int i = 0; i < 4; ++i) {
        #pragma unroll
        for (int off = 4; off > 0; off >>= 1) {
            float ob = __shfl_xor_sync(0xffffffffu, best[i], off, 8);
            int   oi = __shfl_xor_sync(0xffffffffu, bidx[i], off, 8);
            if (ob < best[i] || (ob == best[i] && oi < bidx[i])) {
                best[i] = ob; bidx[i] = oi;
            }
        }
    }

    if (tx == 0) {
        #pragma unroll
        for (int i = 0; i < 4; ++i)
            out[(size_t)b * TC + t0 + ty * 4 + i] = (float)bidx[i];
    }
}

extern "C" void kernel_launch(void* const* d_in, const int* in_sizes, int n_in,
                              void* d_out, int out_size)
{
    // Identify inputs by size: z_e_x has B*D*T = 33,554,432 elems,
    // emb_weight has K*D = 131,072 elems.
    const float* z = (const float*)d_in[0];
    const float* w = (const float*)d_in[1];
    if (n_in >= 2 && in_sizes[0] == KC * DC && in_sizes[1] == BC * DC * TC) {
        z = (const float*)d_in[1];
        w = (const float*)d_in[0];
    }
    float* out = (float*)d_out;               // [B, T], argmin indices as float32

    (void)out_size;

    cudaFuncSetAttribute(vq_argmin_kernel,
                         cudaFuncAttributeMaxDynamicSharedMemorySize,
                         SMEM_FLOATS * sizeof(float));

    dim3 grid(TC / BT, BC);   // (32, 32)
    vq_argmin_kernel<<<grid, 256, SMEM_FLOATS * sizeof(float)>>>(z, w, out);
}